// round 15
// baseline (speedup 1.0000x reference)
#include <cuda_runtime.h>
#include <cuda_fp16.h>
#include <cstdint>

// Problem constants
#define BATCH   32
#define TQ      16
#define NH      16
#define HD      128
#define ED      2048
#define SCACHE  8192
#define NCH     32            // KV split chunks (256 keys each) -> 1024 attn blocks
#define MROWS   512           // BATCH * TQ
#define QROWS   256           // NH * TQ per batch

// ---------------- scratch ----------------
__device__ __half g_xh[MROWS * ED];
__device__ __half g_Wqh[ED * ED];
__device__ __half g_Wkh[HD * ED];
__device__ __half g_Wvh[HD * ED];
__device__ __half g_Woh[ED * ED];
__device__ __half g_Qh[MROWS * ED];
__device__ __half g_Oh[MROWS * ED];
__device__ float  g_Kn[(MROWS + 32) * HD];   // +32 rows padding (OOB-safe tile loads)
__device__ float  g_Vn[(MROWS + 32) * HD];
__device__ __half g_Oparth[(size_t)BATCH * NCH * QROWS * HD];   // 67 MB
__device__ float  g_lpart[BATCH * NCH * QROWS];

// ---------------- helpers ----------------
__device__ __forceinline__ float ex2f(float x) {
    float r;
    asm("ex2.approx.ftz.f32 %0, %1;" : "=f"(r) : "f"(x));
    return r;
}
__device__ __forceinline__ uint32_t h2pack(float a, float b) {
    __half2 h = __floats2half2_rn(a, b);
    return *reinterpret_cast<uint32_t*>(&h);
}
__device__ __forceinline__ void mma16(float c[4], const uint32_t a[4], const uint32_t b[2]) {
    asm volatile(
        "mma.sync.aligned.m16n8k16.row.col.f32.f16.f16.f32 "
        "{%0,%1,%2,%3},{%4,%5,%6,%7},{%8,%9},{%0,%1,%2,%3};\n"
        : "+f"(c[0]), "+f"(c[1]), "+f"(c[2]), "+f"(c[3])
        : "r"(a[0]), "r"(a[1]), "r"(a[2]), "r"(a[3]), "r"(b[0]), "r"(b[1]));
}
__device__ __forceinline__ void ldsm_x2(uint32_t& r0, uint32_t& r1, uint32_t addr) {
    asm volatile("ldmatrix.sync.aligned.m8n8.x2.shared.b16 {%0,%1}, [%2];"
                 : "=r"(r0), "=r"(r1) : "r"(addr));
}
__device__ __forceinline__ void ldsm_x4(uint32_t r[4], uint32_t addr) {
    asm volatile("ldmatrix.sync.aligned.m8n8.x4.shared.b16 {%0,%1,%2,%3}, [%4];"
                 : "=r"(r[0]), "=r"(r[1]), "=r"(r[2]), "=r"(r[3]) : "r"(addr));
}
__device__ __forceinline__ void ldsm_x4_t(uint32_t r[4], uint32_t addr) {
    asm volatile("ldmatrix.sync.aligned.m8n8.x4.trans.shared.b16 {%0,%1,%2,%3}, [%4];"
                 : "=r"(r[0]), "=r"(r[1]), "=r"(r[2]), "=r"(r[3]) : "r"(addr));
}
__device__ __forceinline__ void cp16(uint32_t dst, const void* src) {
    asm volatile("cp.async.ca.shared.global [%0], [%1], 16;\n" :: "r"(dst), "l"(src));
}
__device__ __forceinline__ void cp_commit() { asm volatile("cp.async.commit_group;\n"); }
template <int N>
__device__ __forceinline__ void cp_wait() { asm volatile("cp.async.wait_group %0;\n" :: "n"(N)); }
__device__ __forceinline__ uint32_t smem_u32(const void* p) {
    return (uint32_t)__cvta_generic_to_shared(p);
}

// ---------------- fused fp32 -> fp16 convert (single launch) ----------------
#define CVT_TOTAL4 2490368
__global__ __launch_bounds__(512) void convert_all(
    const float* __restrict__ x,  const float* __restrict__ Wq,
    const float* __restrict__ Wk, const float* __restrict__ Wv,
    const float* __restrict__ Wo)
{
    for (int i = blockIdx.x * 512 + threadIdx.x; i < CVT_TOTAL4;
         i += gridDim.x * 512) {
        const float* src; __half* dst; int j;
        if (i < 262144)        { src = x;  dst = g_xh;  j = i; }
        else if (i < 1310720)  { src = Wq; dst = g_Wqh; j = i - 262144; }
        else if (i < 1376256)  { src = Wk; dst = g_Wkh; j = i - 1310720; }
        else if (i < 1441792)  { src = Wv; dst = g_Wvh; j = i - 1376256; }
        else                   { src = Wo; dst = g_Woh; j = i - 1441792; }
        float4 v = reinterpret_cast<const float4*>(src)[j];
        uint2 o;
        o.x = h2pack(v.x, v.y);
        o.y = h2pack(v.z, v.w);
        reinterpret_cast<uint2*>(dst)[j] = o;
    }
}

// ---------------- GEMM core: 128x64 tile, BK=64, 256 threads (8 warps) ----------------
struct GemmOut {
    void* ptr;
    const float* bias;
    int col0;
    int stride;
    bool half_out;
};

__device__ __forceinline__ void gemm_core(
    const __half* __restrict__ A, const __half* __restrict__ W,
    int bm, int K, const GemmOut& o,
    __half (*Ah)[128 * 64], __half (*Wh)[64 * 64])
{
    const int tid = threadIdx.x;
    const int w = tid >> 5, lane = tid & 31;
    const int lr = lane >> 2, lc = lane & 3;
    const int wm = (w >> 1) * 32, wn = (w & 1) * 32;

    uint32_t sA[2], sW[2];
    sA[0] = smem_u32(&Ah[0][0]); sA[1] = smem_u32(&Ah[1][0]);
    sW[0] = smem_u32(&Wh[0][0]); sW[1] = smem_u32(&Wh[1][0]);

    float acc[2][4][4];
#pragma unroll
    for (int mt = 0; mt < 2; mt++)
#pragma unroll
        for (int nt = 0; nt < 4; nt++)
#pragma unroll
            for (int i = 0; i < 4; i++) acc[mt][nt][i] = 0.f;

    const int NIT = K / 64;
    auto issue = [&](int buf, int k0) {
#pragma unroll
        for (int i = 0; i < 4; i++) {
            int idx = tid + i * 256;
            int r = idx >> 3, c = idx & 7;
            uint32_t off = (uint32_t)((r * 8 + (c ^ (r & 7))) * 16);
            cp16(sA[buf] + off, A + (size_t)(bm + r) * K + k0 + c * 8);
        }
#pragma unroll
        for (int i = 0; i < 2; i++) {
            int idx = tid + i * 256;
            int r = idx >> 3, c = idx & 7;
            uint32_t off = (uint32_t)((r * 8 + (c ^ (r & 7))) * 16);
            cp16(sW[buf] + off, W + (size_t)r * K + k0 + c * 8);
        }
        cp_commit();
    };

    const int arow = lane & 15, msel = lane >> 4;
    const int bxor = lane & 7,  bsel = (lane >> 3) & 1;

    issue(0, 0);
    for (int it = 0; it < NIT; ++it) {
        const int buf = it & 1;
        if (it + 1 < NIT) { issue(buf ^ 1, (it + 1) * 64); cp_wait<1>(); }
        else             { cp_wait<0>(); }
        __syncthreads();

#pragma unroll
        for (int ks = 0; ks < 4; ks++) {
            uint32_t a[2][4], bf[4][2];
#pragma unroll
            for (int mt = 0; mt < 2; mt++) {
                int row = wm + mt * 16 + arow;
                uint32_t addr = sA[buf] +
                    (uint32_t)((row * 8 + ((ks * 2 + msel) ^ (arow & 7))) * 16);
                ldsm_x4(a[mt], addr);
            }
#pragma unroll
            for (int nt = 0; nt < 4; nt++) {
                int row = wn + nt * 8 + bxor;
                uint32_t addr = sW[buf] +
                    (uint32_t)((row * 8 + ((ks * 2 + bsel) ^ bxor)) * 16);
                ldsm_x2(bf[nt][0], bf[nt][1], addr);
            }
#pragma unroll
            for (int mt = 0; mt < 2; mt++)
#pragma unroll
                for (int nt = 0; nt < 4; nt++)
                    mma16(acc[mt][nt], a[mt], bf[nt]);
        }
        __syncthreads();
    }

#pragma unroll
    for (int mt = 0; mt < 2; mt++) {
#pragma unroll
        for (int nt = 0; nt < 4; nt++) {
            int row = bm + wm + mt * 16 + lr;
            int lcol = wn + nt * 8 + 2 * lc;
            int col = o.col0 + lcol;
            float v0 = acc[mt][nt][0] + o.bias[col];
            float v1 = acc[mt][nt][1] + o.bias[col + 1];
            float v2 = acc[mt][nt][2] + o.bias[col];
            float v3 = acc[mt][nt][3] + o.bias[col + 1];
            if (o.half_out) {
                __half* C = (__half*)o.ptr;
                *reinterpret_cast<__half2*>(C + (size_t)row * o.stride + col) =
                    __floats2half2_rn(v0, v1);
                *reinterpret_cast<__half2*>(C + (size_t)(row + 8) * o.stride + col) =
                    __floats2half2_rn(v2, v3);
            } else {
                float* C = (float*)o.ptr;
                C[(size_t)row * o.stride + col]           = v0;
                C[(size_t)row * o.stride + col + 1]       = v1;
                C[(size_t)(row + 8) * o.stride + col]     = v2;
                C[(size_t)(row + 8) * o.stride + col + 1] = v3;
            }
        }
    }
}

__global__ __launch_bounds__(256) void gemm_qkv(
    const float* __restrict__ bq, const float* __restrict__ bk,
    const float* __restrict__ bv)
{
    __shared__ __half Ah[2][128 * 64];
    __shared__ __half Wh[2][64 * 64];

    const int bm = blockIdx.y * 128;
    const int bn = blockIdx.x * 64;

    const __half* W;
    GemmOut o;
    if (bn < ED) {
        W = g_Wqh + (size_t)bn * ED;
        o = { g_Qh, bq, bn, ED, true };
    } else if (bn < ED + HD) {
        int l = bn - ED;
        W = g_Wkh + (size_t)l * ED;
        o = { g_Kn, bk, l, HD, false };
    } else {
        int l = bn - ED - HD;
        W = g_Wvh + (size_t)l * ED;
        o = { g_Vn, bv, l, HD, false };
    }
    gemm_core(g_xh, W, bm, ED, o, Ah, Wh);
}

__global__ __launch_bounds__(256) void gemm_out(
    const float* __restrict__ bo, float* __restrict__ out)
{
    __shared__ __half Ah[2][128 * 64];
    __shared__ __half Wh[2][64 * 64];
    const int bm = blockIdx.y * 128;
    const int bn = blockIdx.x * 64;
    GemmOut o = { out, bo, bn, ED, false };
    gemm_core(g_Oh, g_Woh + (size_t)bn * ED, bm, ED, o, Ah, Wh);
}

// ---------------- fp16 flash attention: 32-key tiles, 256-key chunks ----------------
// grid (NCH, BATCH) = (32, 32) = 1024 blocks; 256 threads = 8 warps;
// warp w handles heads w and w+8. Chunk = 256 keys = 8 tiles of 32;
// last chunk appends one 16-key tile of new keys (half1 skipped).
// dyn smem: kraw 2*16KB | vraw 2*16KB | kh 8KB | vh 8KB  = 80KB
#define ATTN_SMEM (80 * 1024)
__global__ __launch_bounds__(256, 1) void attn_f16(
    const float* __restrict__ Kc, const float* __restrict__ Vc)
{
    extern __shared__ char smem[];
    float* kraw = reinterpret_cast<float*>(smem);            // 2 * 4096 floats
    float* vraw = kraw + 8192;                               // 2 * 4096 floats
    __half* khp = reinterpret_cast<__half*>(vraw + 8192);    // 4096 halves (32x128)
    __half* vhp = khp + 4096;

    const int ch = blockIdx.x;
    const int b  = blockIdx.y;
    const int tid = threadIdx.x;
    const int w = tid >> 5, lane = tid & 31;
    const int gr = lane >> 2, tc = lane & 3;
    const int h0 = w, h1 = w + 8;

    const uint32_t kraw_s = smem_u32(kraw);
    const uint32_t vraw_s = smem_u32(vraw);
    const uint32_t kh_s = smem_u32(khp);
    const uint32_t vh_s = smem_u32(vhp);

    const int ntiles = (ch == NCH - 1) ? 9 : 8;   // 32-key tiles; tile8 = 16 new keys

    auto issue = [&](int it) {
        const uint32_t boff = (uint32_t)(it & 1) * 16384;
        const float *Kg, *Vg;
        if (it < 8) {
            const size_t s0 = (size_t)b * SCACHE + (size_t)ch * 256 + it * 32;
            Kg = Kc + s0 * HD;
            Vg = Vc + s0 * HD;
        } else {
            Kg = g_Kn + (size_t)b * TQ * HD;    // 16 valid rows + padded reads
            Vg = g_Vn + (size_t)b * TQ * HD;
        }
#pragma unroll
        for (int j = 0; j < 4; j++) {
            int idx = tid + j * 256;            // 0..1023 float4 chunks (32x128)
            cp16(kraw_s + boff + (uint32_t)idx * 16, Kg + idx * 4);
            cp16(vraw_s + boff + (uint32_t)idx * 16, Vg + idx * 4);
        }
        cp_commit();
    };

    issue(0);

    // ---- Q fragments in registers for both heads ----
    uint32_t qa0[8][4], qa1[8][4];
    {
        const __half* a0 = g_Qh + ((size_t)(b * TQ + gr))     * ED + h0 * HD;
        const __half* a1 = g_Qh + ((size_t)(b * TQ + gr + 8)) * ED + h0 * HD;
        const __half* c0 = g_Qh + ((size_t)(b * TQ + gr))     * ED + h1 * HD;
        const __half* c1 = g_Qh + ((size_t)(b * TQ + gr + 8)) * ED + h1 * HD;
#pragma unroll
        for (int ks = 0; ks < 8; ks++) {
            int c = ks * 16 + 2 * tc;
            qa0[ks][0] = *reinterpret_cast<const uint32_t*>(a0 + c);
            qa0[ks][1] = *reinterpret_cast<const uint32_t*>(a1 + c);
            qa0[ks][2] = *reinterpret_cast<const uint32_t*>(a0 + c + 8);
            qa0[ks][3] = *reinterpret_cast<const uint32_t*>(a1 + c + 8);
            qa1[ks][0] = *reinterpret_cast<const uint32_t*>(c0 + c);
            qa1[ks][1] = *reinterpret_cast<const uint32_t*>(c1 + c);
            qa1[ks][2] = *reinterpret_cast<const uint32_t*>(c0 + c + 8);
            qa1[ks][3] = *reinterpret_cast<const uint32_t*>(c1 + c + 8);
        }
    }

    float acc0[16][4], acc1[16][4];
#pragma unroll
    for (int nt = 0; nt < 16; nt++)
#pragma unroll
        for (int i = 0; i < 4; i++) { acc0[nt][i] = 0.f; acc1[nt][i] = 0.f; }
    float l00 = 0.f, l01 = 0.f, l10 = 0.f, l11 = 0.f;
    const float F = 0.12752551287f;      // (1/sqrt(128)) * log2(e)

    // ldmatrix x4 lane-address precompute
    const int ksw = lane & 7;
    const int key_k = ((lane >> 4) << 3) + (lane & 7);
    const int kcsub = (lane >> 3) & 1;
    const uint32_t kxbase = kh_s + (uint32_t)key_k * 256;
    const int key_v = (((lane >> 3) & 1) << 3) + (lane & 7);
    const int vnsel = lane >> 4;
    const uint32_t vxbase = vh_s + (uint32_t)key_v * 256;
    const int vsw = key_v & 7;

    for (int it = 0; it < ntiles; ++it) {
        const int buf = it & 1;
        if (it + 1 < ntiles) { issue(it + 1); cp_wait<1>(); }
        else                 { cp_wait<0>(); }
        __syncthreads();

        // ---- vectorized repack: fp32 raw -> fp16 swizzled (16B STS) ----
        {
            const float* kr = kraw + buf * 4096;
            const float* vr = vraw + buf * 4096;
            char* khd = reinterpret_cast<char*>(khp);
            char* vhd = reinterpret_cast<char*>(vhp);
#pragma unroll
            for (int j = 0; j < 2; j++) {
                int id = tid + j * 256;          // 0..511 16B-chunks
                int r = id >> 4, c = id & 15;
                uint32_t off = (uint32_t)(r * 256 + ((c ^ (r & 7)) << 4));
                const float4* ks4 = reinterpret_cast<const float4*>(kr + r * 128 + c * 8);
                const float4* vs4 = reinterpret_cast<const float4*>(vr + r * 128 + c * 8);
                float4 k0 = ks4[0], k1 = ks4[1];
                float4 v0 = vs4[0], v1 = vs4[1];
                uint4 ko = { h2pack(k0.x, k0.y), h2pack(k0.z, k0.w),
                             h2pack(k1.x, k1.y), h2pack(k1.z, k1.w) };
                uint4 vo = { h2pack(v0.x, v0.y), h2pack(v0.z, v0.w),
                             h2pack(v1.x, v1.y), h2pack(v1.z, v1.w) };
                *reinterpret_cast<uint4*>(khd + off) = ko;
                *reinterpret_cast<uint4*>(vhd + off) = vo;
            }
        }
        __syncthreads();

        // ---- two 16-key compute halves (skip half1 on the new-keys tile) ----
#pragma unroll
        for (int half = 0; half < 2; half++) {
            if (half == 1 && it == 8) break;
            const uint32_t hoff = (uint32_t)half * 4096;   // 16 rows * 256B

            float s0[2][4] = {{0.f,0.f,0.f,0.f},{0.f,0.f,0.f,0.f}};
            float s1[2][4] = {{0.f,0.f,0.f,0.f},{0.f,0.f,0.f,0.f}};
#pragma unroll
            for (int ks = 0; ks < 8; ks++) {
                uint32_t kb[4];
                int kc = 2 * ks + kcsub;
                ldsm_x4(kb, kxbase + hoff + (uint32_t)((kc ^ ksw) << 4));
                mma16(s0[0], qa0[ks], kb + 0);
                mma16(s0[1], qa0[ks], kb + 2);
                mma16(s1[0], qa1[ks], kb + 0);
                mma16(s1[1], qa1[ks], kb + 2);
            }

            float p0[2][4], p1[2][4];
#pragma unroll
            for (int nh = 0; nh < 2; nh++)
#pragma unroll
                for (int i = 0; i < 4; i++) {
                    p0[nh][i] = ex2f(s0[nh][i] * F);
                    p1[nh][i] = ex2f(s1[nh][i] * F);
                }

            float r00 = p0[0][0] + p0[0][1] + p0[1][0] + p0[1][1];
            float r01 = p0[0][2] + p0[0][3] + p0[1][2] + p0[1][3];
            float r10 = p1[0][0] + p1[0][1] + p1[1][0] + p1[1][1];
            float r11 = p1[0][2] + p1[0][3] + p1[1][2] + p1[1][3];
            r00 += __shfl_xor_sync(0xffffffffu, r00, 1);
            r00 += __shfl_xor_sync(0xffffffffu, r00, 2);
            r01 += __shfl_xor_sync(0xffffffffu, r01, 1);
            r01 += __shfl_xor_sync(0xffffffffu, r01, 2);
            r10 += __shfl_xor_sync(0xffffffffu, r10, 1);
            r10 += __shfl_xor_sync(0xffffffffu, r10, 2);
            r11 += __shfl_xor_sync(0xffffffffu, r11, 1);
            r11 += __shfl_xor_sync(0xffffffffu, r11, 2);
            l00 += r00; l01 += r01; l10 += r10; l11 += r11;

            uint32_t pa0[4], pa1[4];
            pa0[0] = h2pack(p0[0][0], p0[0][1]);
            pa0[1] = h2pack(p0[0][2], p0[0][3]);
            pa0[2] = h2pack(p0[1][0], p0[1][1]);
            pa0[3] = h2pack(p0[1][2], p0[1][3]);
            pa1[0] = h2pack(p1[0][0], p1[0][1]);
            pa1[1] = h2pack(p1[0][2], p1[0][3]);
            pa1[2] = h2pack(p1[1][0], p1[1][1]);
            pa1[3] = h2pack(p1[1][2], p1[1][3]);

#pragma unroll
            for (int j = 0; j < 8; j++) {
                uint32_t vb[4];
                int chv = 2 * j + vnsel;
                ldsm_x4_t(vb, vxbase + hoff + (uint32_t)((chv ^ vsw) << 4));
                mma16(acc0[2 * j],     pa0, vb + 0);
                mma16(acc0[2 * j + 1], pa0, vb + 2);
                mma16(acc1[2 * j],     pa1, vb + 0);
                mma16(acc1[2 * j + 1], pa1, vb + 2);
            }
        }
    }

    // ---- write unnormalized O (fp16) + l for both heads ----
    {
        const size_t base = (size_t)(b * NCH + ch) * QROWS;
        const size_t o0 = base + h0 * 16;
        const size_t o1 = base + h1 * 16;
        __half* d00 = g_Oparth + (o0 + gr)     * HD;
        __half* d01 = g_Oparth + (o0 + gr + 8) * HD;
        __half* d10 = g_Oparth + (o1 + gr)     * HD;
        __half* d11 = g_Oparth + (o1 + gr + 8) * HD;
#pragma unroll
        for (int nt = 0; nt < 16; nt++) {
            int c = nt * 8 + 2 * tc;
            *reinterpret_cast<uint32_t*>(d00 + c) = h2pack(acc0[nt][0], acc0[nt][1]);
            *reinterpret_cast<uint32_t*>(d01 + c) = h2pack(acc0[nt][2], acc0[nt][3]);
            *reinterpret_cast<uint32_t*>(d10 + c) = h2pack(acc1[nt][0], acc1[nt][1]);
            *reinterpret_cast<uint32_t*>(d11 + c) = h2pack(acc1[nt][2], acc1[nt][3]);
        }
        if (tc == 0) {
            g_lpart[o0 + gr]     = l00;
            g_lpart[o0 + gr + 8] = l01;
            g_lpart[o1 + gr]     = l10;
            g_lpart[o1 + gr + 8] = l11;
        }
    }
}

// ---------------- combine: vectorized (uint4 = 8 halves per thread) ----------------
// grid (512): 131072 threads; thread -> (b, r, d8), d8 = 8 consecutive dims.
__global__ __launch_bounds__(256) void combine_kernel()
{
    const int gidx = blockIdx.x * 256 + threadIdx.x;   // 0 .. 131071
    const int d8 = gidx & 15;                          // 16 uint4 per 128 dims
    const int r  = (gidx >> 4) & (QROWS - 1);
    const int b  = gidx >> 12;
    const int h = r >> 4, t = r & 15;

    float acc[8];
#pragma unroll
    for (int i = 0; i < 8; i++) acc[i] = 0.f;
    float denom = 0.f;

#pragma unroll 8
    for (int c = 0; c < NCH; c++) {
        const size_t row = (size_t)(b * NCH + c) * QROWS + r;
        denom += g_lpart[row];
        uint4 v = *reinterpret_cast<const uint4*>(g_Oparth + row * HD + d8 * 8);
        const __half2* hp = reinterpret_cast<const __half2*>(&v);
#pragma unroll
        for (int i = 0; i < 4; i++) {
            float2 f = __half22float2(hp[i]);
            acc[2 * i]     += f.x;
            acc[2 * i + 1] += f.y;
        }
    }

    float inv = 1.f / denom;
    uint4 o;
    uint32_t* op = reinterpret_cast<uint32_t*>(&o);
#pragma unroll
    for (int i = 0; i < 4; i++)
        op[i] = h2pack(acc[2 * i] * inv, acc[2 * i + 1] * inv);
    *reinterpret_cast<uint4*>(
        g_Oh + ((size_t)(b * TQ + t)) * ED + h * HD + d8 * 8) = o;
}

// ---------------- launch ----------------
extern "C" void kernel_launch(void* const* d_in, const int* in_sizes, int n_in,
                              void* d_out, int out_size)
{
    (void)in_sizes; (void)n_in; (void)out_size;
    const float* x  = (const float*)d_in[0];
    const float* Kc = (const float*)d_in[1];
    const float* Vc = (const float*)d_in[2];
    const float* Wq = (const float*)d_in[3];
    const float* bq = (const float*)d_in[4];
    const float* Wk = (const float*)d_in[5];
    const float* bk = (const float*)d_in[6];
    const float* Wv = (const float*)d_in[7];
    const float* bv = (const float*)d_in[8];
    const float* Wo = (const float*)d_in[9];
    const float* bo = (const float*)d_in[10];
    float* out = (float*)d_out;

    cudaFuncSetAttribute(attn_f16,
                         cudaFuncAttributeMaxDynamicSharedMemorySize, ATTN_SMEM);

    // fused fp32 -> fp16 conversions (single launch)
    convert_all<<<1184, 512>>>(x, Wq, Wk, Wv, Wo);

    // fused QKV projection: 128x64 tiles, 144 blocks (single wave)
    gemm_qkv<<<dim3((ED + 2 * HD) / 64, MROWS / 128), 256>>>(bq, bk, bv);

    // fp16 flash attention: 256-key chunks -> 1024 blocks (7 nearly-full waves)
    attn_f16<<<dim3(NCH, BATCH), 256, ATTN_SMEM>>>(Kc, Vc);

    // merge split-KV partials (vectorized, fp16 output)
    combine_kernel<<<512, 256>>>();

    // output projection: 128x64 tiles, 128 blocks (single wave)
    gemm_out<<<dim3(ED / 64, MROWS / 128), 256>>>(bo, out);
}

// round 16
// speedup vs baseline: 1.0435x; 1.0435x over previous
#include <cuda_runtime.h>
#include <cuda_fp16.h>
#include <cstdint>

// Problem constants
#define BATCH   32
#define TQ      16
#define NH      16
#define HD      128
#define ED      2048
#define SCACHE  8192
#define NCH     16            // KV split chunks (512 keys each)
#define MROWS   512           // BATCH * TQ
#define QROWS   256           // NH * TQ per batch

// ---------------- scratch ----------------
__device__ __half g_xh[MROWS * ED];
__device__ __half g_Wqh[ED * ED];
__device__ __half g_Wkh[HD * ED];
__device__ __half g_Wvh[HD * ED];
__device__ __half g_Woh[ED * ED];
__device__ __half g_Qh[MROWS * ED];
__device__ __half g_Oh[MROWS * ED];
__device__ float  g_Kn[(MROWS + 32) * HD];   // +32 rows padding (OOB-safe tile loads)
__device__ float  g_Vn[(MROWS + 32) * HD];
__device__ __half g_Oparth[(size_t)BATCH * NCH * QROWS * HD];
__device__ float  g_lpart[BATCH * NCH * QROWS];

// ---------------- helpers ----------------
__device__ __forceinline__ float ex2f(float x) {
    float r;
    asm("ex2.approx.ftz.f32 %0, %1;" : "=f"(r) : "f"(x));
    return r;
}
__device__ __forceinline__ uint32_t h2pack(float a, float b) {
    __half2 h = __floats2half2_rn(a, b);
    return *reinterpret_cast<uint32_t*>(&h);
}
__device__ __forceinline__ void mma16(float c[4], const uint32_t a[4], const uint32_t b[2]) {
    asm volatile(
        "mma.sync.aligned.m16n8k16.row.col.f32.f16.f16.f32 "
        "{%0,%1,%2,%3},{%4,%5,%6,%7},{%8,%9},{%0,%1,%2,%3};\n"
        : "+f"(c[0]), "+f"(c[1]), "+f"(c[2]), "+f"(c[3])
        : "r"(a[0]), "r"(a[1]), "r"(a[2]), "r"(a[3]), "r"(b[0]), "r"(b[1]));
}
__device__ __forceinline__ void ldsm_x2(uint32_t& r0, uint32_t& r1, uint32_t addr) {
    asm volatile("ldmatrix.sync.aligned.m8n8.x2.shared.b16 {%0,%1}, [%2];"
                 : "=r"(r0), "=r"(r1) : "r"(addr));
}
__device__ __forceinline__ void ldsm_x4(uint32_t r[4], uint32_t addr) {
    asm volatile("ldmatrix.sync.aligned.m8n8.x4.shared.b16 {%0,%1,%2,%3}, [%4];"
                 : "=r"(r[0]), "=r"(r[1]), "=r"(r[2]), "=r"(r[3]) : "r"(addr));
}
__device__ __forceinline__ void ldsm_x4_t(uint32_t r[4], uint32_t addr) {
    asm volatile("ldmatrix.sync.aligned.m8n8.x4.trans.shared.b16 {%0,%1,%2,%3}, [%4];"
                 : "=r"(r[0]), "=r"(r[1]), "=r"(r[2]), "=r"(r[3]) : "r"(addr));
}
__device__ __forceinline__ void cp16(uint32_t dst, const void* src) {
    asm volatile("cp.async.ca.shared.global [%0], [%1], 16;\n" :: "r"(dst), "l"(src));
}
__device__ __forceinline__ void cp16cg(uint32_t dst, const void* src) {
    asm volatile("cp.async.cg.shared.global [%0], [%1], 16;\n" :: "r"(dst), "l"(src));
}
__device__ __forceinline__ void cp_commit() { asm volatile("cp.async.commit_group;\n"); }
template <int N>
__device__ __forceinline__ void cp_wait() { asm volatile("cp.async.wait_group %0;\n" :: "n"(N)); }
__device__ __forceinline__ uint32_t smem_u32(const void* p) {
    return (uint32_t)__cvta_generic_to_shared(p);
}

// ---------------- fused fp32 -> fp16 convert (single launch) ----------------
#define CVT_TOTAL4 2490368
__global__ __launch_bounds__(512) void convert_all(
    const float* __restrict__ x,  const float* __restrict__ Wq,
    const float* __restrict__ Wk, const float* __restrict__ Wv,
    const float* __restrict__ Wo)
{
    for (int i = blockIdx.x * 512 + threadIdx.x; i < CVT_TOTAL4;
         i += gridDim.x * 512) {
        const float* src; __half* dst; int j;
        if (i < 262144)        { src = x;  dst = g_xh;  j = i; }
        else if (i < 1310720)  { src = Wq; dst = g_Wqh; j = i - 262144; }
        else if (i < 1376256)  { src = Wk; dst = g_Wkh; j = i - 1310720; }
        else if (i < 1441792)  { src = Wv; dst = g_Wvh; j = i - 1376256; }
        else                   { src = Wo; dst = g_Woh; j = i - 1441792; }
        float4 v = __ldcs(reinterpret_cast<const float4*>(src) + j);
        uint2 o;
        o.x = h2pack(v.x, v.y);
        o.y = h2pack(v.z, v.w);
        reinterpret_cast<uint2*>(dst)[j] = o;
    }
}

// ---------------- GEMM core: 128x64 tile, BK=64, 256 threads (8 warps) ----------------
struct GemmOut {
    void* ptr;
    const float* bias;
    int col0;
    int stride;
    bool half_out;
};

__device__ __forceinline__ void gemm_core(
    const __half* __restrict__ A, const __half* __restrict__ W,
    int bm, int K, const GemmOut& o,
    __half (*Ah)[128 * 64], __half (*Wh)[64 * 64])
{
    const int tid = threadIdx.x;
    const int w = tid >> 5, lane = tid & 31;
    const int lr = lane >> 2, lc = lane & 3;
    const int wm = (w >> 1) * 32, wn = (w & 1) * 32;

    uint32_t sA[2], sW[2];
    sA[0] = smem_u32(&Ah[0][0]); sA[1] = smem_u32(&Ah[1][0]);
    sW[0] = smem_u32(&Wh[0][0]); sW[1] = smem_u32(&Wh[1][0]);

    float acc[2][4][4];
#pragma unroll
    for (int mt = 0; mt < 2; mt++)
#pragma unroll
        for (int nt = 0; nt < 4; nt++)
#pragma unroll
            for (int i = 0; i < 4; i++) acc[mt][nt][i] = 0.f;

    const int NIT = K / 64;
    auto issue = [&](int buf, int k0) {
#pragma unroll
        for (int i = 0; i < 4; i++) {
            int idx = tid + i * 256;
            int r = idx >> 3, c = idx & 7;
            uint32_t off = (uint32_t)((r * 8 + (c ^ (r & 7))) * 16);
            cp16(sA[buf] + off, A + (size_t)(bm + r) * K + k0 + c * 8);
        }
#pragma unroll
        for (int i = 0; i < 2; i++) {
            int idx = tid + i * 256;
            int r = idx >> 3, c = idx & 7;
            uint32_t off = (uint32_t)((r * 8 + (c ^ (r & 7))) * 16);
            cp16(sW[buf] + off, W + (size_t)r * K + k0 + c * 8);
        }
        cp_commit();
    };

    const int arow = lane & 15, msel = lane >> 4;
    const int bxor = lane & 7,  bsel = (lane >> 3) & 1;

    issue(0, 0);
    for (int it = 0; it < NIT; ++it) {
        const int buf = it & 1;
        if (it + 1 < NIT) { issue(buf ^ 1, (it + 1) * 64); cp_wait<1>(); }
        else             { cp_wait<0>(); }
        __syncthreads();

#pragma unroll
        for (int ks = 0; ks < 4; ks++) {
            uint32_t a[2][4], bf[4][2];
#pragma unroll
            for (int mt = 0; mt < 2; mt++) {
                int row = wm + mt * 16 + arow;
                uint32_t addr = sA[buf] +
                    (uint32_t)((row * 8 + ((ks * 2 + msel) ^ (arow & 7))) * 16);
                ldsm_x4(a[mt], addr);
            }
#pragma unroll
            for (int nt = 0; nt < 4; nt++) {
                int row = wn + nt * 8 + bxor;
                uint32_t addr = sW[buf] +
                    (uint32_t)((row * 8 + ((ks * 2 + bsel) ^ bxor)) * 16);
                ldsm_x2(bf[nt][0], bf[nt][1], addr);
            }
#pragma unroll
            for (int mt = 0; mt < 2; mt++)
#pragma unroll
                for (int nt = 0; nt < 4; nt++)
                    mma16(acc[mt][nt], a[mt], bf[nt]);
        }
        __syncthreads();
    }

#pragma unroll
    for (int mt = 0; mt < 2; mt++) {
#pragma unroll
        for (int nt = 0; nt < 4; nt++) {
            int row = bm + wm + mt * 16 + lr;
            int lcol = wn + nt * 8 + 2 * lc;
            int col = o.col0 + lcol;
            float v0 = acc[mt][nt][0] + o.bias[col];
            float v1 = acc[mt][nt][1] + o.bias[col + 1];
            float v2 = acc[mt][nt][2] + o.bias[col];
            float v3 = acc[mt][nt][3] + o.bias[col + 1];
            if (o.half_out) {
                __half* C = (__half*)o.ptr;
                *reinterpret_cast<__half2*>(C + (size_t)row * o.stride + col) =
                    __floats2half2_rn(v0, v1);
                *reinterpret_cast<__half2*>(C + (size_t)(row + 8) * o.stride + col) =
                    __floats2half2_rn(v2, v3);
            } else {
                float* C = (float*)o.ptr;
                C[(size_t)row * o.stride + col]           = v0;
                C[(size_t)row * o.stride + col + 1]       = v1;
                C[(size_t)(row + 8) * o.stride + col]     = v2;
                C[(size_t)(row + 8) * o.stride + col + 1] = v3;
            }
        }
    }
}

__global__ __launch_bounds__(256) void gemm_qkv(
    const float* __restrict__ bq, const float* __restrict__ bk,
    const float* __restrict__ bv)
{
    __shared__ __half Ah[2][128 * 64];
    __shared__ __half Wh[2][64 * 64];

    const int bm = blockIdx.y * 128;
    const int bn = blockIdx.x * 64;

    const __half* W;
    GemmOut o;
    if (bn < ED) {
        W = g_Wqh + (size_t)bn * ED;
        o = { g_Qh, bq, bn, ED, true };
    } else if (bn < ED + HD) {
        int l = bn - ED;
        W = g_Wkh + (size_t)l * ED;
        o = { g_Kn, bk, l, HD, false };
    } else {
        int l = bn - ED - HD;
        W = g_Wvh + (size_t)l * ED;
        o = { g_Vn, bv, l, HD, false };
    }
    gemm_core(g_xh, W, bm, ED, o, Ah, Wh);
}

__global__ __launch_bounds__(256) void gemm_out(
    const float* __restrict__ bo, float* __restrict__ out)
{
    __shared__ __half Ah[2][128 * 64];
    __shared__ __half Wh[2][64 * 64];
    const int bm = blockIdx.y * 128;
    const int bn = blockIdx.x * 64;
    GemmOut o = { out, bo, bn, ED, false };
    gemm_core(g_Oh, g_Woh + (size_t)bn * ED, bm, ED, o, Ah, Wh);
}

// ---------------- fp16 flash attention: 32-key tiles, 2 heads/warp (R13 base) ----------------
// grid (NCH, BATCH) = 512 blocks; 256 threads = 8 warps; warp w = heads w, w+8.
// New-keys tile is owned by chunk (b & 15), spreading long blocks across the grid.
// dyn smem: kraw 2*16KB | vraw 2*16KB | kh 8KB | vh 8KB  = 80KB
#define ATTN_SMEM (80 * 1024)
__global__ __launch_bounds__(256, 1) void attn_f16(
    const float* __restrict__ Kc, const float* __restrict__ Vc)
{
    extern __shared__ char smem[];
    float* kraw = reinterpret_cast<float*>(smem);            // 2 * 4096 floats
    float* vraw = kraw + 8192;                               // 2 * 4096 floats
    __half* khp = reinterpret_cast<__half*>(vraw + 8192);    // 4096 halves (32x128)
    __half* vhp = khp + 4096;

    const int ch = blockIdx.x;
    const int b  = blockIdx.y;
    const int tid = threadIdx.x;
    const int w = tid >> 5, lane = tid & 31;
    const int gr = lane >> 2, tc = lane & 3;
    const int h0 = w, h1 = w + 8;

    const uint32_t kraw_s = smem_u32(kraw);
    const uint32_t vraw_s = smem_u32(vraw);
    const uint32_t kh_s = smem_u32(khp);
    const uint32_t vh_s = smem_u32(vhp);

    // new-keys tile assigned to chunk (b & 15): long blocks spread over the grid
    const int ntiles = (ch == (b & 15)) ? 17 : 16;   // tile 16 = 16 new keys

    auto issue = [&](int it) {
        const uint32_t boff = (uint32_t)(it & 1) * 16384;
        const float *Kg, *Vg;
        if (it < 16) {
            const size_t s0 = (size_t)b * SCACHE + (size_t)ch * 512 + it * 32;
            Kg = Kc + s0 * HD;
            Vg = Vc + s0 * HD;
        } else {
            Kg = g_Kn + (size_t)b * TQ * HD;    // 16 valid rows + padded reads
            Vg = g_Vn + (size_t)b * TQ * HD;
        }
#pragma unroll
        for (int j = 0; j < 4; j++) {
            int idx = tid + j * 256;            // 0..1023 float4 chunks (32x128)
            cp16cg(kraw_s + boff + (uint32_t)idx * 16, Kg + idx * 4);
            cp16cg(vraw_s + boff + (uint32_t)idx * 16, Vg + idx * 4);
        }
        cp_commit();
    };

    issue(0);

    // ---- Q fragments in registers for both heads ----
    uint32_t qa0[8][4], qa1[8][4];
    {
        const __half* a0 = g_Qh + ((size_t)(b * TQ + gr))     * ED + h0 * HD;
        const __half* a1 = g_Qh + ((size_t)(b * TQ + gr + 8)) * ED + h0 * HD;
        const __half* c0 = g_Qh + ((size_t)(b * TQ + gr))     * ED + h1 * HD;
        const __half* c1 = g_Qh + ((size_t)(b * TQ + gr + 8)) * ED + h1 * HD;
#pragma unroll
        for (int ks = 0; ks < 8; ks++) {
            int c = ks * 16 + 2 * tc;
            qa0[ks][0] = *reinterpret_cast<const uint32_t*>(a0 + c);
            qa0[ks][1] = *reinterpret_cast<const uint32_t*>(a1 + c);
            qa0[ks][2] = *reinterpret_cast<const uint32_t*>(a0 + c + 8);
            qa0[ks][3] = *reinterpret_cast<const uint32_t*>(a1 + c + 8);
            qa1[ks][0] = *reinterpret_cast<const uint32_t*>(c0 + c);
            qa1[ks][1] = *reinterpret_cast<const uint32_t*>(c1 + c);
            qa1[ks][2] = *reinterpret_cast<const uint32_t*>(c0 + c + 8);
            qa1[ks][3] = *reinterpret_cast<const uint32_t*>(c1 + c + 8);
        }
    }

    float acc0[16][4], acc1[16][4];
#pragma unroll
    for (int nt = 0; nt < 16; nt++)
#pragma unroll
        for (int i = 0; i < 4; i++) { acc0[nt][i] = 0.f; acc1[nt][i] = 0.f; }
    float l00 = 0.f, l01 = 0.f, l10 = 0.f, l11 = 0.f;
    const float F = 0.12752551287f;      // (1/sqrt(128)) * log2(e)

    // ldmatrix x4 lane-address precompute
    const int ksw = lane & 7;
    const int key_k = ((lane >> 4) << 3) + (lane & 7);
    const int kcsub = (lane >> 3) & 1;
    const uint32_t kxbase = kh_s + (uint32_t)key_k * 256;
    const int key_v = (((lane >> 3) & 1) << 3) + (lane & 7);
    const int vnsel = lane >> 4;
    const uint32_t vxbase = vh_s + (uint32_t)key_v * 256;
    const int vsw = key_v & 7;

    for (int it = 0; it < ntiles; ++it) {
        const int buf = it & 1;
        if (it + 1 < ntiles) { issue(it + 1); cp_wait<1>(); }
        else                 { cp_wait<0>(); }
        __syncthreads();

        // ---- vectorized repack: fp32 raw -> fp16 swizzled (16B STS) ----
        {
            const float* kr = kraw + buf * 4096;
            const float* vr = vraw + buf * 4096;
            char* khd = reinterpret_cast<char*>(khp);
            char* vhd = reinterpret_cast<char*>(vhp);
#pragma unroll
            for (int j = 0; j < 2; j++) {
                int id = tid + j * 256;          // 0..511 16B-chunks
                int r = id >> 4, c = id & 15;
                uint32_t off = (uint32_t)(r * 256 + ((c ^ (r & 7)) << 4));
                const float4* ks4 = reinterpret_cast<const float4*>(kr + r * 128 + c * 8);
                const float4* vs4 = reinterpret_cast<const float4*>(vr + r * 128 + c * 8);
                float4 k0 = ks4[0], k1 = ks4[1];
                float4 v0 = vs4[0], v1 = vs4[1];
                uint4 ko = { h2pack(k0.x, k0.y), h2pack(k0.z, k0.w),
                             h2pack(k1.x, k1.y), h2pack(k1.z, k1.w) };
                uint4 vo = { h2pack(v0.x, v0.y), h2pack(v0.z, v0.w),
                             h2pack(v1.x, v1.y), h2pack(v1.z, v1.w) };
                *reinterpret_cast<uint4*>(khd + off) = ko;
                *reinterpret_cast<uint4*>(vhd + off) = vo;
            }
        }
        __syncthreads();

        // ---- two 16-key compute halves (skip half1 on the new-keys tile) ----
#pragma unroll
        for (int half = 0; half < 2; half++) {
            if (half == 1 && it == 16) break;
            const uint32_t hoff = (uint32_t)half * 4096;   // 16 rows * 256B

            float s0[2][4] = {{0.f,0.f,0.f,0.f},{0.f,0.f,0.f,0.f}};
            float s1[2][4] = {{0.f,0.f,0.f,0.f},{0.f,0.f,0.f,0.f}};
#pragma unroll
            for (int ks = 0; ks < 8; ks++) {
                uint32_t kb[4];
                int kc = 2 * ks + kcsub;
                ldsm_x4(kb, kxbase + hoff + (uint32_t)((kc ^ ksw) << 4));
                mma16(s0[0], qa0[ks], kb + 0);
                mma16(s0[1], qa0[ks], kb + 2);
                mma16(s1[0], qa1[ks], kb + 0);
                mma16(s1[1], qa1[ks], kb + 2);
            }

            float p0[2][4], p1[2][4];
#pragma unroll
            for (int nh = 0; nh < 2; nh++)
#pragma unroll
                for (int i = 0; i < 4; i++) {
                    p0[nh][i] = ex2f(s0[nh][i] * F);
                    p1[nh][i] = ex2f(s1[nh][i] * F);
                }

            float r00 = p0[0][0] + p0[0][1] + p0[1][0] + p0[1][1];
            float r01 = p0[0][2] + p0[0][3] + p0[1][2] + p0[1][3];
            float r10 = p1[0][0] + p1[0][1] + p1[1][0] + p1[1][1];
            float r11 = p1[0][2] + p1[0][3] + p1[1][2] + p1[1][3];
            r00 += __shfl_xor_sync(0xffffffffu, r00, 1);
            r00 += __shfl_xor_sync(0xffffffffu, r00, 2);
            r01 += __shfl_xor_sync(0xffffffffu, r01, 1);
            r01 += __shfl_xor_sync(0xffffffffu, r01, 2);
            r10 += __shfl_xor_sync(0xffffffffu, r10, 1);
            r10 += __shfl_xor_sync(0xffffffffu, r10, 2);
            r11 += __shfl_xor_sync(0xffffffffu, r11, 1);
            r11 += __shfl_xor_sync(0xffffffffu, r11, 2);
            l00 += r00; l01 += r01; l10 += r10; l11 += r11;

            uint32_t pa0[4], pa1[4];
            pa0[0] = h2pack(p0[0][0], p0[0][1]);
            pa0[1] = h2pack(p0[0][2], p0[0][3]);
            pa0[2] = h2pack(p0[1][0], p0[1][1]);
            pa0[3] = h2pack(p0[1][2], p0[1][3]);
            pa1[0] = h2pack(p1[0][0], p1[0][1]);
            pa1[1] = h2pack(p1[0][2], p1[0][3]);
            pa1[2] = h2pack(p1[1][0], p1[1][1]);
            pa1[3] = h2pack(p1[1][2], p1[1][3]);

#pragma unroll
            for (int j = 0; j < 8; j++) {
                uint32_t vb[4];
                int chv = 2 * j + vnsel;
                ldsm_x4_t(vb, vxbase + hoff + (uint32_t)((chv ^ vsw) << 4));
                mma16(acc0[2 * j],     pa0, vb + 0);
                mma16(acc0[2 * j + 1], pa0, vb + 2);
                mma16(acc1[2 * j],     pa1, vb + 0);
                mma16(acc1[2 * j + 1], pa1, vb + 2);
            }
        }
    }

    // ---- write unnormalized O (fp16) + l for both heads ----
    {
        const size_t base = (size_t)(b * NCH + ch) * QROWS;
        const size_t o0 = base + h0 * 16;
        const size_t o1 = base + h1 * 16;
        __half* d00 = g_Oparth + (o0 + gr)     * HD;
        __half* d01 = g_Oparth + (o0 + gr + 8) * HD;
        __half* d10 = g_Oparth + (o1 + gr)     * HD;
        __half* d11 = g_Oparth + (o1 + gr + 8) * HD;
#pragma unroll
        for (int nt = 0; nt < 16; nt++) {
            int c = nt * 8 + 2 * tc;
            *reinterpret_cast<uint32_t*>(d00 + c) = h2pack(acc0[nt][0], acc0[nt][1]);
            *reinterpret_cast<uint32_t*>(d01 + c) = h2pack(acc0[nt][2], acc0[nt][3]);
            *reinterpret_cast<uint32_t*>(d10 + c) = h2pack(acc1[nt][0], acc1[nt][1]);
            *reinterpret_cast<uint32_t*>(d11 + c) = h2pack(acc1[nt][2], acc1[nt][3]);
        }
        if (tc == 0) {
            g_lpart[o0 + gr]     = l00;
            g_lpart[o0 + gr + 8] = l01;
            g_lpart[o1 + gr]     = l10;
            g_lpart[o1 + gr + 8] = l11;
        }
    }
}

// ---------------- combine: vectorized + streaming loads ----------------
// grid (512): 131072 threads; thread -> (b, r, d8), d8 = 8 consecutive dims.
__global__ __launch_bounds__(256) void combine_kernel()
{
    const int gidx = blockIdx.x * 256 + threadIdx.x;   // 0 .. 131071
    const int d8 = gidx & 15;                          // 16 uint4 per 128 dims
    const int r  = (gidx >> 4) & (QROWS - 1);
    const int b  = gidx >> 12;
    const int h = r >> 4, t = r & 15;

    float acc[8];
#pragma unroll
    for (int i = 0; i < 8; i++) acc[i] = 0.f;
    float denom = 0.f;

#pragma unroll
    for (int c = 0; c < NCH; c++) {
        const size_t row = (size_t)(b * NCH + c) * QROWS + r;
        denom += __ldcs(g_lpart + row);
        uint4 v = __ldcs(reinterpret_cast<const uint4*>(g_Oparth + row * HD + d8 * 8));
        const __half2* hp = reinterpret_cast<const __half2*>(&v);
#pragma unroll
        for (int i = 0; i < 4; i++) {
            float2 f = __half22float2(hp[i]);
            acc[2 * i]     += f.x;
            acc[2 * i + 1] += f.y;
        }
    }

    float inv = 1.f / denom;
    uint4 o;
    uint32_t* op = reinterpret_cast<uint32_t*>(&o);
#pragma unroll
    for (int i = 0; i < 4; i++)
        op[i] = h2pack(acc[2 * i] * inv, acc[2 * i + 1] * inv);
    *reinterpret_cast<uint4*>(
        g_Oh + ((size_t)(b * TQ + t)) * ED + h * HD + d8 * 8) = o;
}

// ---------------- launch ----------------
extern "C" void kernel_launch(void* const* d_in, const int* in_sizes, int n_in,
                              void* d_out, int out_size)
{
    (void)in_sizes; (void)n_in; (void)out_size;
    const float* x  = (const float*)d_in[0];
    const float* Kc = (const float*)d_in[1];
    const float* Vc = (const float*)d_in[2];
    const float* Wq = (const float*)d_in[3];
    const float* bq = (const float*)d_in[4];
    const float* Wk = (const float*)d_in[5];
    const float* bk = (const float*)d_in[6];
    const float* Wv = (const float*)d_in[7];
    const float* bv = (const float*)d_in[8];
    const float* Wo = (const float*)d_in[9];
    const float* bo = (const float*)d_in[10];
    float* out = (float*)d_out;

    cudaFuncSetAttribute(attn_f16,
                         cudaFuncAttributeMaxDynamicSharedMemorySize, ATTN_SMEM);

    // fused fp32 -> fp16 conversions (single launch)
    convert_all<<<1184, 512>>>(x, Wq, Wk, Wv, Wo);

    // fused QKV projection: 128x64 tiles, 144 blocks (single wave)
    gemm_qkv<<<dim3((ED + 2 * HD) / 64, MROWS / 128), 256>>>(bq, bk, bv);

    // fp16 flash attention: 512-key chunks, new-keys tile spread across chunks
    attn_f16<<<dim3(NCH, BATCH), 256, ATTN_SMEM>>>(Kc, Vc);

    // merge split-KV partials (vectorized, streaming, fp16 output)
    combine_kernel<<<512, 256>>>();

    // output projection: 128x64 tiles, 128 blocks (single wave)
    gemm_out<<<dim3(ED / 64, MROWS / 128), 256>>>(bo, out);
}